// round 2
// baseline (speedup 1.0000x reference)
#include <cuda_runtime.h>
#include <math.h>

// Problem constants (fixed by the dataset)
#define B_   16
#define N_   64
#define T_   768
#define NJ_  17
#define MA_  512
#define BN_  (B_ * N_)          // 1024
#define ROW_ (NJ_ * 3)          // 51 floats per joint-row
#define RTOT_ (BN_ * MA_)       // 524288 output rows

// Scratch: inverse map  table[bn*512 + age] = t  (or -1 if no valid detection)
__device__ int g_table[BN_ * MA_];

// Sparse posetrack->h36m remap: per output joint, up to 4 (src joint, weight).
// Padded entries have weight 0 (and point at joint 0, harmless).
__constant__ unsigned char c_j[NJ_][4] = {
    {11,12, 0, 0},  // 0: pelvis = mean(hips)
    {12, 0, 0, 0},  // 1
    {14, 0, 0, 0},  // 2
    {16, 0, 0, 0},  // 3
    {11, 0, 0, 0},  // 4
    {13, 0, 0, 0},  // 5
    {15, 0, 0, 0},  // 6
    { 5, 6,11,12},  // 7: torso = mean(pelvis, thorax)
    { 5, 6, 0, 0},  // 8: thorax = mean(shoulders)
    { 1, 0, 0, 0},  // 9
    { 2, 0, 0, 0},  // 10
    { 5, 0, 0, 0},  // 11
    { 7, 0, 0, 0},  // 12
    { 9, 0, 0, 0},  // 13
    { 6, 0, 0, 0},  // 14
    { 8, 0, 0, 0},  // 15
    {10, 0, 0, 0},  // 16
};
__constant__ float c_w[NJ_][4] = {
    {0.5f, 0.5f, 0.f, 0.f},
    {1.f, 0.f, 0.f, 0.f},
    {1.f, 0.f, 0.f, 0.f},
    {1.f, 0.f, 0.f, 0.f},
    {1.f, 0.f, 0.f, 0.f},
    {1.f, 0.f, 0.f, 0.f},
    {1.f, 0.f, 0.f, 0.f},
    {0.25f, 0.25f, 0.25f, 0.25f},
    {0.5f, 0.5f, 0.f, 0.f},
    {1.f, 0.f, 0.f, 0.f},
    {1.f, 0.f, 0.f, 0.f},
    {1.f, 0.f, 0.f, 0.f},
    {1.f, 0.f, 0.f, 0.f},
    {1.f, 0.f, 0.f, 0.f},
    {1.f, 0.f, 0.f, 0.f},
    {1.f, 0.f, 0.f, 0.f},
    {1.f, 0.f, 0.f, 0.f},
};

// ---------------------------------------------------------------------------
// Kernel 1: reset inverse map to -1 (vectorized int4 stores, 2 MB)
// ---------------------------------------------------------------------------
__global__ void init_table_k() {
    int i = blockIdx.x * blockDim.x + threadIdx.x;   // over RTOT_/4 int4s
    if (i < RTOT_ / 4)
        ((int4*)g_table)[i] = make_int4(-1, -1, -1, -1);
}

// ---------------------------------------------------------------------------
// Kernel 2: scatter valid ages -> table[bn][age] = t
// Valid = finite && 0 <= age < 512. Ages are unique per (b,n), so plain store.
// ---------------------------------------------------------------------------
__global__ void scatter_k(const float* __restrict__ ages) {
    int i = blockIdx.x * blockDim.x + threadIdx.x;   // over BN_*T_
    if (i >= BN_ * T_) return;
    float a = __ldg(&ages[i]);
    if (isfinite(a) && a >= 0.0f && a < (float)MA_) {
        int bn = i / T_;
        int t  = i - bn * T_;
        g_table[bn * MA_ + __float2int_rz(a)] = t;
    }
}

// ---------------------------------------------------------------------------
// Kernel 3: dense gather over output rows.
// One warp per row per iteration; grid-stride so each lane's sparse-M
// coefficients are hoisted into registers ONCE (avoids divergent LDC replays
// in the hot loop). Lanes cover elements [lane] and [lane+32] of the 51-float
// row.
// ---------------------------------------------------------------------------
__global__ void __launch_bounds__(256) gather_k(const float* __restrict__ kp,
                                                float* __restrict__ out) {
    __shared__ float s[8][ROW_ + 1];  // +1 pad
    const int warpIn = threadIdx.x >> 5;
    const int lane   = threadIdx.x & 31;
    float* sv = s[warpIn];
    const bool has1 = (lane < (ROW_ - 32));  // lane < 19 handles second half

    // Hoist per-lane remap constants into registers (one-time divergent reads).
    int   jb0[4]; float w0[4]; int ch0;
    {
        int e = lane;
        int i = e / 3; ch0 = e - 3 * i;
        #pragma unroll
        for (int k = 0; k < 4; k++) { jb0[k] = (int)c_j[i][k] * 3; w0[k] = c_w[i][k]; }
    }
    int   jb1[4] = {0,0,0,0}; float w1[4] = {0,0,0,0}; int ch1 = 0;
    if (has1) {
        int e = lane + 32;
        int i = e / 3; ch1 = e - 3 * i;
        #pragma unroll
        for (int k = 0; k < 4; k++) { jb1[k] = (int)c_j[i][k] * 3; w1[k] = c_w[i][k]; }
    }

    const int nWarps = gridDim.x * 8;
    for (int row = blockIdx.x * 8 + warpIn; row < RTOT_; row += nWarps) {
        const int bn = row >> 9;               // row / 512
        const int p  = row & (MA_ - 1);        // output age slot (already flipped)
        const int t  = g_table[bn * MA_ + (MA_ - 1 - p)];
        float* orow = out + row * ROW_;

        if (t < 0) {                           // no detection -> zeros
            orow[lane] = 0.0f;
            if (has1) orow[lane + 32] = 0.0f;
            continue;
        }

        const float* irow = kp + (bn * T_ + t) * ROW_;
        sv[lane] = irow[lane];
        if (has1) sv[lane + 32] = irow[lane + 32];
        __syncwarp();

        // element e = lane
        {
            float conf = 0.f, val = 0.f;
            #pragma unroll
            for (int k = 0; k < 4; k++) {
                conf += w0[k] * sv[jb0[k] + 2];
                val  += w0[k] * sv[jb0[k] + ch0];
            }
            float r = (ch0 < 2) ? (2.0f * val - 1.0f) : conf;  // xy->[-1,1]; c passthrough
            orow[lane] = (conf == 0.0f) ? 0.0f : r;            // zero-conf mask
        }
        // element e = lane + 32
        if (has1) {
            float conf = 0.f, val = 0.f;
            #pragma unroll
            for (int k = 0; k < 4; k++) {
                conf += w1[k] * sv[jb1[k] + 2];
                val  += w1[k] * sv[jb1[k] + ch1];
            }
            float r = (ch1 < 2) ? (2.0f * val - 1.0f) : conf;
            orow[lane + 32] = (conf == 0.0f) ? 0.0f : r;
        }
        __syncwarp();  // protect smem before next iteration overwrites
    }
}

// ---------------------------------------------------------------------------
extern "C" void kernel_launch(void* const* d_in, const int* in_sizes, int n_in,
                              void* d_out, int out_size) {
    const float* kp   = (const float*)d_in[0];  // [16,64,768,17,3]
    const float* ages = (const float*)d_in[1];  // [16,64,768,1]
    float* out = (float*)d_out;                 // [16,64,512,17,3]

    init_table_k<<<(RTOT_ / 4 + 255) / 256, 256>>>();         // 512 blocks
    scatter_k<<<(BN_ * T_ + 255) / 256, 256>>>(ages);         // 3072 blocks
    gather_k<<<1024, 256>>>(kp, out);                         // 8192 warps, grid-stride
}

// round 4
// speedup vs baseline: 1.4810x; 1.4810x over previous
#include <cuda_runtime.h>
#include <math.h>

// Problem constants (fixed by the dataset)
#define B_    16
#define N_    64
#define T_    768
#define NJ_   17
#define MA_   512
#define BN_   (B_ * N_)            // 1024
#define ROW_  (NJ_ * 3)            // 51 floats per joint-row
#define CHUNK_ROWS 32              // rows staged per block-iteration
#define NCHUNK (MA_ / CHUNK_ROWS)  // 16
#define CHUNK_F (CHUNK_ROWS * ROW_)      // 1632 floats
#define CHUNK_V4 (CHUNK_F / 4)           // 408 float4 (1632 % 4 == 0)

// Sparse posetrack->h36m remap: per output joint, up to 4 (src joint, weight).
__constant__ unsigned char c_j[NJ_][4] = {
    {11,12, 0, 0},  // 0: pelvis = mean(hips)
    {12, 0, 0, 0},  // 1
    {14, 0, 0, 0},  // 2
    {16, 0, 0, 0},  // 3
    {11, 0, 0, 0},  // 4
    {13, 0, 0, 0},  // 5
    {15, 0, 0, 0},  // 6
    { 5, 6,11,12},  // 7: torso = mean(pelvis, thorax)
    { 5, 6, 0, 0},  // 8: thorax = mean(shoulders)
    { 1, 0, 0, 0},  // 9
    { 2, 0, 0, 0},  // 10
    { 5, 0, 0, 0},  // 11
    { 7, 0, 0, 0},  // 12
    { 9, 0, 0, 0},  // 13
    { 6, 0, 0, 0},  // 14
    { 8, 0, 0, 0},  // 15
    {10, 0, 0, 0},  // 16
};
__constant__ float c_w[NJ_][4] = {
    {0.5f, 0.5f, 0.f, 0.f},
    {1.f, 0.f, 0.f, 0.f},
    {1.f, 0.f, 0.f, 0.f},
    {1.f, 0.f, 0.f, 0.f},
    {1.f, 0.f, 0.f, 0.f},
    {1.f, 0.f, 0.f, 0.f},
    {1.f, 0.f, 0.f, 0.f},
    {0.25f, 0.25f, 0.25f, 0.25f},
    {0.5f, 0.5f, 0.f, 0.f},
    {1.f, 0.f, 0.f, 0.f},
    {1.f, 0.f, 0.f, 0.f},
    {1.f, 0.f, 0.f, 0.f},
    {1.f, 0.f, 0.f, 0.f},
    {1.f, 0.f, 0.f, 0.f},
    {1.f, 0.f, 0.f, 0.f},
    {1.f, 0.f, 0.f, 0.f},
    {1.f, 0.f, 0.f, 0.f},
};

// ---------------------------------------------------------------------------
// Fused kernel: one block per (b,n).
//  Phase 0: build smem inverse table age->t from this bn's 768 ages.
//  Main loop (16 chunks of 32 rows):
//    - each of 8 warps gathers 4 rows (8 independent predicated LDGs -> MLP 8)
//    - remap/normalize/mask into double-buffered smem chunk
//    - block-wide aligned float4 streaming store (1 __syncthreads per chunk)
// ---------------------------------------------------------------------------
__global__ void __launch_bounds__(256)
fused_tok_k(const float* __restrict__ kp,
            const float* __restrict__ ages,
            float* __restrict__ out) {
    __shared__ int   tbl[MA_];                       // 2 KB inverse map
    __shared__ float sin_[8][4][ROW_ + 1];           // per-warp staged input rows
    __shared__ float sout[2][CHUNK_F];               // double-buffered output chunk

    const int bn   = blockIdx.x;
    const int tid  = threadIdx.x;
    const int warp = tid >> 5;
    const int lane = tid & 31;
    const bool has1 = (lane < (ROW_ - 32));          // lane < 19

    // ---- Phase 0: inverse table in smem -------------------------------
    tbl[tid] = -1; tbl[tid + 256] = -1;
    __syncthreads();
    {
        const float* ag = ages + bn * T_;
        #pragma unroll
        for (int i = tid; i < T_; i += 256) {
            float a = __ldg(&ag[i]);
            if (isfinite(a) && a >= 0.0f && a < (float)MA_)
                tbl[__float2int_rz(a)] = i;          // ages unique per bn
        }
    }

    // ---- Hoist per-lane remap constants into registers ----------------
    int   jb0[4]; float w0[4]; int ch0;
    {
        int e = lane, i = e / 3; ch0 = e - 3 * i;
        #pragma unroll
        for (int k = 0; k < 4; k++) { jb0[k] = (int)c_j[i][k] * 3; w0[k] = c_w[i][k]; }
    }
    int   jb1[4] = {0,0,0,0}; float w1[4] = {0,0,0,0}; int ch1 = 0;
    if (has1) {
        int e = lane + 32, i = e / 3; ch1 = e - 3 * i;
        #pragma unroll
        for (int k = 0; k < 4; k++) { jb1[k] = (int)c_j[i][k] * 3; w1[k] = c_w[i][k]; }
    }
    __syncthreads();                                 // table ready

    const float* kpb  = kp  + (size_t)bn * T_ * ROW_;
    float*       outb = out + (size_t)bn * MA_ * ROW_;

    for (int chunk = 0; chunk < NCHUNK; chunk++) {
        float* obuf = sout[chunk & 1];

        // -- gather 4 rows per warp: issue all 8 LDGs before any use ----
        int t[4];
        #pragma unroll
        for (int r = 0; r < 4; r++) {
            int p = chunk * CHUNK_ROWS + warp * 4 + r;   // output slot
            t[r] = tbl[MA_ - 1 - p];                     // time-flip here
        }
        float a[4], b[4];
        #pragma unroll
        for (int r = 0; r < 4; r++) {
            const float* irow = kpb + t[r] * ROW_;
            a[r] = (t[r] >= 0)          ? __ldg(&irow[lane])      : 0.0f;
            b[r] = (t[r] >= 0 && has1)  ? __ldg(&irow[lane + 32]) : 0.0f;
        }
        #pragma unroll
        for (int r = 0; r < 4; r++) {
            sin_[warp][r][lane] = a[r];
            if (has1) sin_[warp][r][lane + 32] = b[r];
        }
        __syncwarp();

        // -- remap + normalize + conf mask into output chunk ------------
        #pragma unroll
        for (int r = 0; r < 4; r++) {
            const float* sv = sin_[warp][r];
            const int orow = warp * 4 + r;               // row within chunk
            {
                float conf = 0.f, val = 0.f;
                #pragma unroll
                for (int k = 0; k < 4; k++) {
                    conf += w0[k] * sv[jb0[k] + 2];
                    val  += w0[k] * sv[jb0[k] + ch0];
                }
                float res = (ch0 < 2) ? (2.0f * val - 1.0f) : conf;
                obuf[orow * ROW_ + lane] = (conf == 0.0f) ? 0.0f : res;
            }
            if (has1) {
                float conf = 0.f, val = 0.f;
                #pragma unroll
                for (int k = 0; k < 4; k++) {
                    conf += w1[k] * sv[jb1[k] + 2];
                    val  += w1[k] * sv[jb1[k] + ch1];
                }
                float res = (ch1 < 2) ? (2.0f * val - 1.0f) : conf;
                obuf[orow * ROW_ + lane + 32] = (conf == 0.0f) ? 0.0f : res;
            }
        }
        __syncthreads();                                 // chunk complete

        // -- aligned vectorized streaming store -------------------------
        // (double buffer: per-thread program order puts these reads of
        //  sout[chunk&1] before the NEXT chunk's barrier; the buffer is
        //  rewritten only after that barrier. One barrier per chunk.)
        float4*       dst = (float4*)(outb + chunk * CHUNK_F);
        const float4* src = (const float4*)obuf;
        #pragma unroll
        for (int i = tid; i < CHUNK_V4; i += 256)
            dst[i] = src[i];
    }
}

// ---------------------------------------------------------------------------
extern "C" void kernel_launch(void* const* d_in, const int* in_sizes, int n_in,
                              void* d_out, int out_size) {
    const float* kp   = (const float*)d_in[0];  // [16,64,768,17,3]
    const float* ages = (const float*)d_in[1];  // [16,64,768,1]
    float* out = (float*)d_out;                 // [16,64,512,17,3]

    fused_tok_k<<<BN_, 256>>>(kp, ages, out);   // 1024 blocks, one per (b,n)
}

// round 5
// speedup vs baseline: 1.6810x; 1.1350x over previous
#include <cuda_runtime.h>
#include <math.h>

// Problem constants (fixed by the dataset)
#define B_    16
#define N_    64
#define T_    768
#define NJ_   17
#define MA_   512
#define BN_   (B_ * N_)            // 1024
#define ROW_  (NJ_ * 3)            // 51 floats per joint-row
#define CHUNK_ROWS 32              // rows per block-iteration (4 per warp)
#define NCHUNK (MA_ / CHUNK_ROWS)  // 16

// ---------------------------------------------------------------------------
// Task-ordered remap tables. 17 "jobs" = output joints in custom order:
// 14 copies first, then 2-term blends (joints 0, 8), then the 4-term (joint 7).
// Task index = job*3 + channel. Phase A = tasks 0..31 (all copies),
// phase B = tasks 32..50 (10 copies + 6 two-term + 3 four-term).
// All blends are uniform means -> weight = 1/nt exactly.
// ---------------------------------------------------------------------------
__constant__ unsigned char jb_dst[17] = {1,2,3,4,5,6,9,10,11,12,13,14,15,16, 0, 8, 7};
__constant__ unsigned char jb_nt[17]  = {1,1,1,1,1,1,1,1,1,1,1,1,1,1, 2, 2, 4};
__constant__ unsigned char jb_src[17][4] = {
    {12,0,0,0},{14,0,0,0},{16,0,0,0},{11,0,0,0},{13,0,0,0},{15,0,0,0},
    { 1,0,0,0},{ 2,0,0,0},{ 5,0,0,0},{ 7,0,0,0},{ 9,0,0,0},{ 6,0,0,0},
    { 8,0,0,0},{10,0,0,0},
    {11,12,0,0},   // joint 0: pelvis = mean(hips)
    { 5, 6,0,0},   // joint 8: thorax = mean(shoulders)
    { 5, 6,11,12}  // joint 7: torso = mean of 4
};

// ---------------------------------------------------------------------------
// Fused kernel: one block per (b,n).
//  Phase 0: smem inverse table age->t from this bn's 768 ages (one barrier).
//  Main loop: each warp independently handles 4 rows per chunk:
//    8 predicated LDGs in flight (MLP 8) -> smem stage -> sparse remap
//    (copies 1-term, blends predicated) -> direct scalar STG (coalesces in L2).
//  No __syncthreads in the main loop; 2 __syncwarp per chunk.
// ---------------------------------------------------------------------------
__global__ void __launch_bounds__(256)
fused_tok_k(const float* __restrict__ kp,
            const float* __restrict__ ages,
            float* __restrict__ out) {
    __shared__ int   tbl[MA_];               // 2 KB inverse map
    __shared__ float sin_[8][4][ROW_ + 1];   // per-warp staged input rows (6.6 KB)

    const int bn   = blockIdx.x;
    const int tid  = threadIdx.x;
    const int warp = tid >> 5;
    const int lane = tid & 31;
    const bool has1 = (lane < (ROW_ - 32));  // lane < 19

    // ---- Phase 0: inverse table in smem -------------------------------
    tbl[tid] = -1; tbl[tid + 256] = -1;
    __syncthreads();
    {
        const float* ag = ages + bn * T_;
        #pragma unroll
        for (int i = tid; i < T_; i += 256) {
            float a = __ldg(&ag[i]);
            if (isfinite(a) && a >= 0.0f && a < (float)MA_)
                tbl[__float2int_rz(a)] = i;  // ages unique per bn
        }
    }

    // ---- Hoist per-lane task descriptors into registers ---------------
    // Phase A: task = lane (copy, weight 1).
    int dstA, sA, coffA; bool xyA;
    {
        int job = lane / 3, ch = lane - 3 * job;
        dstA  = 3 * (int)jb_dst[job] + ch;
        sA    = 3 * (int)jb_src[job][0] + ch;
        coffA = 2 - ch;
        xyA   = (ch < 2);
    }
    // Phase B: task = 32 + lane (lane < 19).
    int dstB = 0, sB0 = 0, sB1 = 0, sB2 = 0, sB3 = 0, coffB = 0, ntB = 1;
    float wB = 1.0f; bool xyB = false;
    if (has1) {
        int task = 32 + lane;
        int job = task / 3, ch = task - 3 * job;
        dstB  = 3 * (int)jb_dst[job] + ch;
        ntB   = (int)jb_nt[job];
        wB    = 1.0f / (float)ntB;           // 1, 0.5, 0.25 (exact)
        sB0   = 3 * (int)jb_src[job][0] + ch;
        sB1   = 3 * (int)jb_src[job][1] + ch;
        sB2   = 3 * (int)jb_src[job][2] + ch;
        sB3   = 3 * (int)jb_src[job][3] + ch;
        coffB = 2 - ch;
        xyB   = (ch < 2);
    }
    __syncthreads();                          // table ready

    const float* kpb  = kp  + (size_t)bn * T_ * ROW_;
    float*       outb = out + (size_t)bn * MA_ * ROW_;

    for (int chunk = 0; chunk < NCHUNK; chunk++) {
        const int row0 = chunk * CHUNK_ROWS + warp * 4;

        // -- gather 4 rows: all 8 LDGs issued before any use (MLP 8) ----
        int t[4];
        #pragma unroll
        for (int r = 0; r < 4; r++)
            t[r] = tbl[MA_ - 1 - (row0 + r)];        // time-flip
        float a[4], b[4];
        #pragma unroll
        for (int r = 0; r < 4; r++) {
            const float* irow = kpb + t[r] * ROW_;
            a[r] = (t[r] >= 0)         ? __ldg(&irow[lane])      : 0.0f;
            b[r] = (t[r] >= 0 && has1) ? __ldg(&irow[lane + 32]) : 0.0f;
        }
        __syncwarp();   // prev chunk's compute reads done before overwrite
        #pragma unroll
        for (int r = 0; r < 4; r++) {
            sin_[warp][r][lane] = a[r];
            if (has1) sin_[warp][r][lane + 32] = b[r];
        }
        __syncwarp();   // staged rows visible warp-wide

        // -- remap + normalize + mask, store direct to global -----------
        // (invalid rows staged as zeros -> conf==0 -> exact zero output)
        #pragma unroll
        for (int r = 0; r < 4; r++) {
            const float* sv = sin_[warp][r];
            float* orow = outb + (size_t)(row0 + r) * ROW_;
            // Phase A: pure copy tasks (weight 1)
            {
                float v = sv[sA];
                float c = sv[sA + coffA];
                float res = xyA ? fmaf(v, 2.0f, -1.0f) : c;
                orow[dstA] = (c == 0.0f) ? 0.0f : res;
            }
            // Phase B: 10 copies + blends (predicated extra terms)
            if (has1) {
                float v = sv[sB0];
                float c = sv[sB0 + coffB];
                if (ntB > 1) {                       // 9 of 19 lanes
                    v += sv[sB1];
                    c += sv[sB1 + coffB];
                }
                if (ntB > 2) {                       // 3 of 19 lanes
                    v += sv[sB2] + sv[sB3];
                    c += sv[sB2 + coffB] + sv[sB3 + coffB];
                }
                float res = xyB ? fmaf(v, 2.0f * wB, -1.0f) : c * wB;
                orow[dstB] = (c == 0.0f) ? 0.0f : res;
            }
        }
    }
}

// ---------------------------------------------------------------------------
extern "C" void kernel_launch(void* const* d_in, const int* in_sizes, int n_in,
                              void* d_out, int out_size) {
    const float* kp   = (const float*)d_in[0];  // [16,64,768,17,3]
    const float* ages = (const float*)d_in[1];  // [16,64,768,1]
    float* out = (float*)d_out;                 // [16,64,512,17,3]

    fused_tok_k<<<BN_, 256>>>(kp, ages, out);   // 1024 blocks, one per (b,n)
}